// round 5
// baseline (speedup 1.0000x reference)
#include <cuda_runtime.h>
#include <cuda_fp16.h>

static constexpr int MAX_NC  = 50000;
static constexpr int MAX_NG  = 3000;
static constexpr int D       = 64;
static constexpr int MAX_E   = 3000000;
static constexpr int MAX_EGG = 1048576;

// fp16 weighted source features (wf = feat * cj * mask); row = 128 B.
__device__ __half g_wf_c[MAX_NC * D];
__device__ __half g_wf_grev[MAX_NG * D];
__device__ __half g_wf_ggg[MAX_NG * D];

// Bucket machinery: per-relation offsets / cursors / sorted src lists.
__device__ int g_off_cg[MAX_NG + 1];
__device__ int g_cur_cg[MAX_NG];        // histogram counts, then write cursor
__device__ int g_off_gg[MAX_NG + 1];
__device__ int g_cur_gg[MAX_NG];
__device__ int g_off_gc[MAX_NC + 1];
__device__ int g_cur_gc[MAX_NC];
__device__ int g_srt_cg[MAX_E];
__device__ int g_srt_gc[MAX_E];
__device__ int g_srt_gg[MAX_EGG];

// ---------------------------------------------------------------------------
// wf = fp16(feat * cj * mask)
// ---------------------------------------------------------------------------
__global__ void weight_rows1(const float* __restrict__ feat,
                             const float* __restrict__ cj,
                             const float* __restrict__ mask,
                             __half* __restrict__ out, int n_vec) {
    int i = blockIdx.x * blockDim.x + threadIdx.x;
    if (i >= n_vec) return;
    int row = i >> 4;
    float w = __ldg(cj + row) * __ldg(mask + row);
    float4 v = __ldg(((const float4*)feat) + i);
    ((__half2*)out)[i * 2 + 0] = __floats2half2_rn(v.x * w, v.y * w);
    ((__half2*)out)[i * 2 + 1] = __floats2half2_rn(v.z * w, v.w * w);
}

__global__ void weight_rows2(const float* __restrict__ feat,
                             const float* __restrict__ cj1, const float* __restrict__ m1,
                             const float* __restrict__ cj2, const float* __restrict__ m2,
                             __half* __restrict__ out1, __half* __restrict__ out2,
                             int n_vec) {
    int i = blockIdx.x * blockDim.x + threadIdx.x;
    if (i >= n_vec) return;
    int row = i >> 4;
    float4 v = __ldg(((const float4*)feat) + i);
    float w1 = __ldg(cj1 + row) * __ldg(m1 + row);
    float w2 = __ldg(cj2 + row) * __ldg(m2 + row);
    ((__half2*)out1)[i * 2 + 0] = __floats2half2_rn(v.x * w1, v.y * w1);
    ((__half2*)out1)[i * 2 + 1] = __floats2half2_rn(v.z * w1, v.w * w1);
    ((__half2*)out2)[i * 2 + 0] = __floats2half2_rn(v.x * w2, v.y * w2);
    ((__half2*)out2)[i * 2 + 1] = __floats2half2_rn(v.z * w2, v.w * w2);
}

// ---------------------------------------------------------------------------
// Counting sort by destination: histogram -> exclusive scan -> scatter.
// ---------------------------------------------------------------------------
__global__ void hist_kernel(const int* __restrict__ dst, int* __restrict__ cnt, int nE) {
    int e = blockIdx.x * blockDim.x + threadIdx.x;
    if (e < nE) atomicAdd(cnt + __ldg(dst + e), 1);
}

// Single-block exclusive scan over n counts (n <= 50176 with 1024 threads).
// Reads cnt, writes off[0..n] and resets cnt[i] to the segment start (cursor).
__global__ void exscan_kernel(int* __restrict__ cnt, int* __restrict__ off, int n) {
    __shared__ int warptot[32];
    int tid  = threadIdx.x;
    int lane = tid & 31, wid = tid >> 5;
    int L  = (n + 1023) / 1024;
    int lo = tid * L;
    int hi = lo + L; if (hi > n) hi = n; if (lo > n) lo = n;

    int s = 0;
    for (int i = lo; i < hi; i++) s += cnt[i];

    // block-wide exclusive scan of per-thread sums
    int v = s;
    #pragma unroll
    for (int d = 1; d < 32; d <<= 1) {
        int t = __shfl_up_sync(~0u, v, d);
        if (lane >= d) v += t;
    }
    if (lane == 31) warptot[wid] = v;
    __syncthreads();
    if (wid == 0) {
        int w = warptot[lane];
        #pragma unroll
        for (int d = 1; d < 32; d <<= 1) {
            int t = __shfl_up_sync(~0u, w, d);
            if (lane >= d) w += t;
        }
        warptot[lane] = w;
    }
    __syncthreads();
    int base = (wid > 0 ? warptot[wid - 1] : 0) + (v - s);

    int run = base;
    for (int i = lo; i < hi; i++) {
        int c = cnt[i];           // read before overwrite (cnt reused as cursor)
        off[i] = run;
        cnt[i] = run;
        run += c;
    }
    if (tid == 1023) off[n] = run;
}

__global__ void bucket_scatter(const int* __restrict__ src,
                               const int* __restrict__ dst,
                               int* __restrict__ cur,
                               int* __restrict__ srt, int nE) {
    int e = blockIdx.x * blockDim.x + threadIdx.x;
    if (e >= nE) return;
    int d = __ldg(dst + e);
    int pos = atomicAdd(cur + d, 1);
    srt[pos] = __ldg(src + e);
}

// ---------------------------------------------------------------------------
// Pull kernels: one warp per destination row. Lane l owns dims [2l, 2l+1].
// Per edge: one 128-B fp16 row gather (1 wavefront), fp32 register accumulate.
// No atomics, single coalesced 256-B output write.
// ---------------------------------------------------------------------------
__device__ __forceinline__ void seg_accum(const int* __restrict__ srt,
                                          int b, int e,
                                          const __half* __restrict__ wf,
                                          int lane, float& ax, float& ay) {
    int i = b;
    for (; i + 8 <= e; i += 8) {
        unsigned r[8];
        #pragma unroll
        for (int k = 0; k < 8; k++) {
            int s = __ldg(srt + i + k);
            r[k] = __ldg((const unsigned*)(wf + (size_t)s * D) + lane);
        }
        #pragma unroll
        for (int k = 0; k < 8; k++) {
            float2 f = __half22float2(*reinterpret_cast<const __half2*>(&r[k]));
            ax += f.x; ay += f.y;
        }
    }
    for (; i < e; i++) {
        int s = __ldg(srt + i);
        unsigned r = __ldg((const unsigned*)(wf + (size_t)s * D) + lane);
        float2 f = __half22float2(*reinterpret_cast<const __half2*>(&r));
        ax += f.x; ay += f.y;
    }
}

// g_out = 0.5*ci_gene*sum(cg) + 0.5*cii_gene*sum(gg)
__global__ void pull_gene(const int* __restrict__ srt_cg, const int* __restrict__ off_cg,
                          const int* __restrict__ srt_gg, const int* __restrict__ off_gg,
                          const __half* __restrict__ wf_c, const __half* __restrict__ wf_gg,
                          const float* __restrict__ ci, const float* __restrict__ cii,
                          float* __restrict__ out, int ng) {
    int warp = (blockIdx.x * blockDim.x + threadIdx.x) >> 5;
    int lane = threadIdx.x & 31;
    if (warp >= ng) return;
    float ax = 0.f, ay = 0.f, bx = 0.f, by = 0.f;
    seg_accum(srt_cg, __ldg(off_cg + warp), __ldg(off_cg + warp + 1), wf_c, lane, ax, ay);
    seg_accum(srt_gg, __ldg(off_gg + warp), __ldg(off_gg + warp + 1), wf_gg, lane, bx, by);
    float w1 = 0.5f * __ldg(ci + warp);
    float w2 = 0.5f * __ldg(cii + warp);
    float2 o = make_float2(ax * w1 + bx * w2, ay * w1 + by * w2);
    ((float2*)(out + (size_t)warp * D))[lane] = o;
}

// c_out = ci_cell * sum(gc)
__global__ void pull_cell(const int* __restrict__ srt, const int* __restrict__ off,
                          const __half* __restrict__ wf,
                          const float* __restrict__ ci,
                          float* __restrict__ out, int nc) {
    int warp = (blockIdx.x * blockDim.x + threadIdx.x) >> 5;
    int lane = threadIdx.x & 31;
    if (warp >= nc) return;
    float ax = 0.f, ay = 0.f;
    seg_accum(srt, __ldg(off + warp), __ldg(off + warp + 1), wf, lane, ax, ay);
    float w = __ldg(ci + warp);
    ((float2*)(out + (size_t)warp * D))[lane] = make_float2(ax * w, ay * w);
}

// ---------------------------------------------------------------------------
// kernel_launch
// Inputs: c_feat, g_feat, cj_cell, ci_cell, cj_gene, ci_gene, cjj_gene,
//   cii_gene, mask_exp, mask_rev, mask_gg,
//   src_cg, dst_cg, src_gc, dst_gc, src_gg, dst_gg
// Output: concat(c_out [NC*D], g_out [NG*D]) float32.
// ---------------------------------------------------------------------------
extern "C" void kernel_launch(void* const* d_in, const int* in_sizes, int n_in,
                              void* d_out, int out_size) {
    const float* c_feat   = (const float*)d_in[0];
    const float* g_feat   = (const float*)d_in[1];
    const float* cj_cell  = (const float*)d_in[2];
    const float* ci_cell  = (const float*)d_in[3];
    const float* cj_gene  = (const float*)d_in[4];
    const float* ci_gene  = (const float*)d_in[5];
    const float* cjj_gene = (const float*)d_in[6];
    const float* cii_gene = (const float*)d_in[7];
    const float* mask_exp = (const float*)d_in[8];
    const float* mask_rev = (const float*)d_in[9];
    const float* mask_gg  = (const float*)d_in[10];
    const int*   src_cg   = (const int*)d_in[11];
    const int*   dst_cg   = (const int*)d_in[12];
    const int*   src_gc   = (const int*)d_in[13];
    const int*   dst_gc   = (const int*)d_in[14];
    const int*   src_gg   = (const int*)d_in[15];
    const int*   dst_gg   = (const int*)d_in[16];

    const int nc   = in_sizes[0] / D;
    const int ng   = in_sizes[1] / D;
    const int e_cg = in_sizes[11];
    const int e_gc = in_sizes[13];
    const int e_gg = in_sizes[15];

    float* c_out = (float*)d_out;                  // [nc, D]
    float* g_out = (float*)d_out + (size_t)nc * D; // [ng, D]

    __half *wf_c, *wf_grev, *wf_ggg;
    int *off_cg, *cur_cg, *off_gg, *cur_gg, *off_gc, *cur_gc;
    int *srt_cg, *srt_gc, *srt_gg;
    cudaGetSymbolAddress((void**)&wf_c,    g_wf_c);
    cudaGetSymbolAddress((void**)&wf_grev, g_wf_grev);
    cudaGetSymbolAddress((void**)&wf_ggg,  g_wf_ggg);
    cudaGetSymbolAddress((void**)&off_cg,  g_off_cg);
    cudaGetSymbolAddress((void**)&cur_cg,  g_cur_cg);
    cudaGetSymbolAddress((void**)&off_gg,  g_off_gg);
    cudaGetSymbolAddress((void**)&cur_gg,  g_cur_gg);
    cudaGetSymbolAddress((void**)&off_gc,  g_off_gc);
    cudaGetSymbolAddress((void**)&cur_gc,  g_cur_gc);
    cudaGetSymbolAddress((void**)&srt_cg,  g_srt_cg);
    cudaGetSymbolAddress((void**)&srt_gc,  g_srt_gc);
    cudaGetSymbolAddress((void**)&srt_gg,  g_srt_gg);

    // 1) zero histogram counters
    cudaMemsetAsync(cur_cg, 0, (size_t)ng * sizeof(int));
    cudaMemsetAsync(cur_gg, 0, (size_t)ng * sizeof(int));
    cudaMemsetAsync(cur_gc, 0, (size_t)nc * sizeof(int));

    // 2) fp16 weighted source features
    {
        int nv = nc * (D / 4);
        weight_rows1<<<(nv + 255) / 256, 256>>>(c_feat, cj_cell, mask_exp, wf_c, nv);
    }
    {
        int nv = ng * (D / 4);
        weight_rows2<<<(nv + 255) / 256, 256>>>(g_feat, cj_gene, mask_rev,
                                                cjj_gene, mask_gg,
                                                wf_grev, wf_ggg, nv);
    }

    // 3) histograms
    hist_kernel<<<(e_cg + 255) / 256, 256>>>(dst_cg, cur_cg, e_cg);
    hist_kernel<<<(e_gg + 255) / 256, 256>>>(dst_gg, cur_gg, e_gg);
    hist_kernel<<<(e_gc + 255) / 256, 256>>>(dst_gc, cur_gc, e_gc);

    // 4) exclusive scans (single block each) -> offsets + cursors
    exscan_kernel<<<1, 1024>>>(cur_cg, off_cg, ng);
    exscan_kernel<<<1, 1024>>>(cur_gg, off_gg, ng);
    exscan_kernel<<<1, 1024>>>(cur_gc, off_gc, nc);

    // 5) counting-sort src indices into dst buckets
    bucket_scatter<<<(e_cg + 255) / 256, 256>>>(src_cg, dst_cg, cur_cg, srt_cg, e_cg);
    bucket_scatter<<<(e_gg + 255) / 256, 256>>>(src_gg, dst_gg, cur_gg, srt_gg, e_gg);
    bucket_scatter<<<(e_gc + 255) / 256, 256>>>(src_gc, dst_gc, cur_gc, srt_gc, e_gc);

    // 6) pull: register-accumulated segment sums, ci/alpha in epilogue
    {
        int threads = ng * 32;
        pull_gene<<<(threads + 255) / 256, 256>>>(srt_cg, off_cg, srt_gg, off_gg,
                                                  wf_c, wf_ggg, ci_gene, cii_gene,
                                                  g_out, ng);
    }
    {
        int threads = nc * 32;
        pull_cell<<<(threads + 255) / 256, 256>>>(srt_gc, off_gc, wf_grev,
                                                  ci_cell, c_out, nc);
    }
}

// round 9
// speedup vs baseline: 1.8819x; 1.8819x over previous
#include <cuda_runtime.h>
#include <cuda_fp16.h>

static constexpr int MAX_NC = 50000;
static constexpr int MAX_NG = 3000;
static constexpr int D      = 64;
static constexpr int EPT    = 4;   // edges per 16-lane group (one int4 of indices)

// fp16 weighted source features (wf = feat * cj * mask); row = 128 B.
__device__ __half g_wf_c[MAX_NC * D];      // cells, weighted for 'exp'
__device__ __half g_wf_grev[MAX_NG * D];   // genes, weighted for 'reverse-exp'
__device__ __half g_wf_ggg[MAX_NG * D];    // genes, weighted for 'co-exp'
// Raw segment-sum accumulator for the cg relation (ci deferred to epilogue).
__device__ float g_acc_gexp[MAX_NG * D];

// ---------------------------------------------------------------------------
// wf = fp16(feat * cj * mask)
// ---------------------------------------------------------------------------
__global__ void weight_rows1(const float* __restrict__ feat,
                             const float* __restrict__ cj,
                             const float* __restrict__ mask,
                             __half* __restrict__ out, int n_vec) {
    int i = blockIdx.x * blockDim.x + threadIdx.x;
    if (i >= n_vec) return;
    int row = i >> 4;
    float w = __ldg(cj + row) * __ldg(mask + row);
    float4 v = __ldg(((const float4*)feat) + i);
    ((__half2*)out)[i * 2 + 0] = __floats2half2_rn(v.x * w, v.y * w);
    ((__half2*)out)[i * 2 + 1] = __floats2half2_rn(v.z * w, v.w * w);
}

__global__ void weight_rows2(const float* __restrict__ feat,
                             const float* __restrict__ cj1, const float* __restrict__ m1,
                             const float* __restrict__ cj2, const float* __restrict__ m2,
                             __half* __restrict__ out1, __half* __restrict__ out2,
                             int n_vec) {
    int i = blockIdx.x * blockDim.x + threadIdx.x;
    if (i >= n_vec) return;
    int row = i >> 4;
    float4 v = __ldg(((const float4*)feat) + i);
    float w1 = __ldg(cj1 + row) * __ldg(m1 + row);
    float w2 = __ldg(cj2 + row) * __ldg(m2 + row);
    ((__half2*)out1)[i * 2 + 0] = __floats2half2_rn(v.x * w1, v.y * w1);
    ((__half2*)out1)[i * 2 + 1] = __floats2half2_rn(v.z * w1, v.w * w1);
    ((__half2*)out2)[i * 2 + 0] = __floats2half2_rn(v.x * w2, v.y * w2);
    ((__half2*)out2)[i * 2 + 1] = __floats2half2_rn(v.z * w2, v.w * w2);
}

// ---------------------------------------------------------------------------
// RAW edge scatter: acc[dst] += wf[src]. No per-edge ci load, no FMA.
// 16-lane group = EPT consecutive edges; per lane: 8-B fp16 gather, f32
// convert, one red.global.add.v4.f32.
// ---------------------------------------------------------------------------
__global__ void edge_scatter_raw(const int* __restrict__ src,
                                 const int* __restrict__ dst,
                                 const __half* __restrict__ wf,
                                 float* __restrict__ acc,
                                 int nE) {
    unsigned t = blockIdx.x * blockDim.x + threadIdx.x;
    int group = (int)(t >> 4);
    int lane  = (int)(t & 15u);
    int e0 = group * EPT;
    if (e0 >= nE) return;

    if (e0 + EPT <= nE) {
        int4 s4 = __ldg((const int4*)(src + e0));
        int4 d4 = __ldg((const int4*)(dst + e0));
        int s[EPT] = {s4.x, s4.y, s4.z, s4.w};
        int d[EPT] = {d4.x, d4.y, d4.z, d4.w};

        uint2 raw[EPT];
        #pragma unroll
        for (int k = 0; k < EPT; k++)
            raw[k] = __ldg((const uint2*)(wf + (size_t)s[k] * D) + lane);

        #pragma unroll
        for (int k = 0; k < EPT; k++) {
            float2 f0 = __half22float2(*reinterpret_cast<const __half2*>(&raw[k].x));
            float2 f1 = __half22float2(*reinterpret_cast<const __half2*>(&raw[k].y));
            float* p = acc + (size_t)d[k] * D + lane * 4;
            asm volatile("red.global.add.v4.f32 [%0], {%1,%2,%3,%4};"
                         :: "l"(p), "f"(f0.x), "f"(f0.y), "f"(f1.x), "f"(f1.y)
                         : "memory");
        }
    } else {
        for (int e = e0; e < nE; e++) {
            int s = __ldg(src + e);
            int d = __ldg(dst + e);
            uint2 raw = __ldg((const uint2*)(wf + (size_t)s * D) + lane);
            float2 f0 = __half22float2(*reinterpret_cast<const __half2*>(&raw.x));
            float2 f1 = __half22float2(*reinterpret_cast<const __half2*>(&raw.y));
            float* p = acc + (size_t)d * D + lane * 4;
            asm volatile("red.global.add.v4.f32 [%0], {%1,%2,%3,%4};"
                         :: "l"(p), "f"(f0.x), "f"(f0.y), "f"(f1.x), "f"(f1.y)
                         : "memory");
        }
    }
}

// ---------------------------------------------------------------------------
// Scaled edge scatter (used only for the tiny gg relation, 100K edges):
// out[dst] += alpha * ci[dst] * wf[src].
// ---------------------------------------------------------------------------
__global__ void edge_scatter_scaled(const int* __restrict__ src,
                                    const int* __restrict__ dst,
                                    const __half* __restrict__ wf,
                                    const float* __restrict__ ci,
                                    float* __restrict__ out,
                                    int nE, float alpha) {
    unsigned t = blockIdx.x * blockDim.x + threadIdx.x;
    int group = (int)(t >> 4);
    int lane  = (int)(t & 15u);
    int e0 = group * EPT;
    if (e0 >= nE) return;

    int e_hi = e0 + EPT < nE ? e0 + EPT : nE;
    for (int e = e0; e < e_hi; e++) {
        int s = __ldg(src + e);
        int d = __ldg(dst + e);
        float scale = alpha * __ldg(ci + d);
        uint2 raw = __ldg((const uint2*)(wf + (size_t)s * D) + lane);
        float2 f0 = __half22float2(*reinterpret_cast<const __half2*>(&raw.x));
        float2 f1 = __half22float2(*reinterpret_cast<const __half2*>(&raw.y));
        float* p = out + (size_t)d * D + lane * 4;
        asm volatile("red.global.add.v4.f32 [%0], {%1,%2,%3,%4};"
                     :: "l"(p), "f"(f0.x * scale), "f"(f0.y * scale),
                        "f"(f1.x * scale), "f"(f1.y * scale)
                     : "memory");
    }
}

// ---------------------------------------------------------------------------
// Epilogues.
// c_out *= ci_cell (in place).
// ---------------------------------------------------------------------------
__global__ void scale_inplace(float* __restrict__ buf,
                              const float* __restrict__ ci, int n_vec) {
    int i = blockIdx.x * blockDim.x + threadIdx.x;
    if (i >= n_vec) return;
    int row = i >> 4;
    float w = __ldg(ci + row);
    float4 v = ((float4*)buf)[i];
    ((float4*)buf)[i] = make_float4(v.x * w, v.y * w, v.z * w, v.w * w);
}

// g_out += 0.5 * ci_gene * acc (in place; g_out already holds the gg term).
__global__ void add_scaled(float* __restrict__ out,
                           const float* __restrict__ acc,
                           const float* __restrict__ ci, int n_vec) {
    int i = blockIdx.x * blockDim.x + threadIdx.x;
    if (i >= n_vec) return;
    int row = i >> 4;
    float w = 0.5f * __ldg(ci + row);
    float4 a = ((const float4*)acc)[i];
    float4 o = ((float4*)out)[i];
    ((float4*)out)[i] = make_float4(o.x + a.x * w, o.y + a.y * w,
                                    o.z + a.z * w, o.w + a.w * w);
}

// ---------------------------------------------------------------------------
// kernel_launch
// Inputs: c_feat, g_feat, cj_cell, ci_cell, cj_gene, ci_gene, cjj_gene,
//   cii_gene, mask_exp, mask_rev, mask_gg,
//   src_cg, dst_cg, src_gc, dst_gc, src_gg, dst_gg
// Output: concat(c_out [NC*D], g_out [NG*D]) float32.
// ---------------------------------------------------------------------------
extern "C" void kernel_launch(void* const* d_in, const int* in_sizes, int n_in,
                              void* d_out, int out_size) {
    const float* c_feat   = (const float*)d_in[0];
    const float* g_feat   = (const float*)d_in[1];
    const float* cj_cell  = (const float*)d_in[2];
    const float* ci_cell  = (const float*)d_in[3];
    const float* cj_gene  = (const float*)d_in[4];
    const float* ci_gene  = (const float*)d_in[5];
    const float* cjj_gene = (const float*)d_in[6];
    const float* cii_gene = (const float*)d_in[7];
    const float* mask_exp = (const float*)d_in[8];
    const float* mask_rev = (const float*)d_in[9];
    const float* mask_gg  = (const float*)d_in[10];
    const int*   src_cg   = (const int*)d_in[11];
    const int*   dst_cg   = (const int*)d_in[12];
    const int*   src_gc   = (const int*)d_in[13];
    const int*   dst_gc   = (const int*)d_in[14];
    const int*   src_gg   = (const int*)d_in[15];
    const int*   dst_gg   = (const int*)d_in[16];

    const int nc   = in_sizes[0] / D;
    const int ng   = in_sizes[1] / D;
    const int e_cg = in_sizes[11];
    const int e_gc = in_sizes[13];
    const int e_gg = in_sizes[15];

    float* c_out = (float*)d_out;                  // [nc, D]
    float* g_out = (float*)d_out + (size_t)nc * D; // [ng, D]

    __half *wf_c, *wf_grev, *wf_ggg;
    float *acc_gexp;
    cudaGetSymbolAddress((void**)&wf_c,     g_wf_c);
    cudaGetSymbolAddress((void**)&wf_grev,  g_wf_grev);
    cudaGetSymbolAddress((void**)&wf_ggg,   g_wf_ggg);
    cudaGetSymbolAddress((void**)&acc_gexp, g_acc_gexp);

    // 1) zero accumulators (d_out is poisoned; acc_gexp is 768 KB)
    cudaMemsetAsync(d_out, 0, (size_t)out_size * sizeof(float));
    cudaMemsetAsync(acc_gexp, 0, (size_t)ng * D * sizeof(float));

    // 2) fp16 weighted source features
    {
        int nv = nc * (D / 4);
        weight_rows1<<<(nv + 255) / 256, 256>>>(c_feat, cj_cell, mask_exp, wf_c, nv);
    }
    {
        int nv = ng * (D / 4);
        weight_rows2<<<(nv + 255) / 256, 256>>>(g_feat, cj_gene, mask_rev,
                                                cjj_gene, mask_gg,
                                                wf_grev, wf_ggg, nv);
    }

    // 3) edge scatters
    auto blocks_for = [](int nE) {
        long long groups = (nE + EPT - 1) / EPT;
        return (int)((groups * 16 + 255) / 256);
    };
    // cell -> gene ('exp'): raw sum into scratch (ci_gene deferred)
    edge_scatter_raw<<<blocks_for(e_cg), 256>>>(src_cg, dst_cg, wf_c, acc_gexp, e_cg);
    // gene -> cell ('reverse-exp'): raw sum directly into c_out (ci_cell deferred)
    edge_scatter_raw<<<blocks_for(e_gc), 256>>>(src_gc, dst_gc, wf_grev, c_out, e_gc);
    // gene -> gene ('co-exp'): tiny relation, keep per-edge fold, write to g_out
    edge_scatter_scaled<<<blocks_for(e_gg), 256>>>(src_gg, dst_gg, wf_ggg,
                                                   cii_gene, g_out, e_gg, 0.5f);

    // 4) epilogues
    {
        int nv = nc * (D / 4);
        scale_inplace<<<(nv + 255) / 256, 256>>>(c_out, ci_cell, nv);
    }
    {
        int nv = ng * (D / 4);
        add_scaled<<<(nv + 255) / 256, 256>>>(g_out, acc_gexp, ci_gene, nv);
    }
}